// round 3
// baseline (speedup 1.0000x reference)
#include <cuda_runtime.h>

#define NN 50000
#define NE 1600000
#define DD 32
static constexpr float Hstep = 0.1f;

// ---------------- static device scratch (no allocations allowed) ----------------
__device__ int   g_is64;
__device__ int   g_deg[NN];
__device__ int   g_cur[NN];
__device__ int   g_rowptr[2][NN + 1];
__device__ int   g_col[2][NE];
__device__ float g_val[2][NE];
__device__ float g_dis[2][NN];
__device__ float g_tmp[2][NN * DD];   // ping-pong (y @ W) buffers
__device__ float g_x[NN * DD];
__device__ float g_ksum[NN * DD];

// ---------------- dtype probe: int64 edge buffers have zero odd words ----------------
__global__ void k_probe(const int* __restrict__ w) {
    __shared__ int anynz;
    if (threadIdx.x == 0) anynz = 0;
    __syncthreads();
    // Check odd words of the first 1024 (putative) int64 elements.
    if (w[2 * threadIdx.x + 1] != 0) atomicOr(&anynz, 1);
    __syncthreads();
    if (threadIdx.x == 0) g_is64 = (anynz == 0) ? 1 : 0;
}

// ---------------- edge readers (dtype-agnostic) ----------------
__device__ __forceinline__ int edge_src(const void* ei, int e, int is64) {
    if (is64) return (int)((const long long*)ei)[e];
    return ((const int*)ei)[e];
}
__device__ __forceinline__ int edge_dst(const void* ei, int e, int is64) {
    if (is64) return (int)((const long long*)ei)[NE + e];
    return ((const int*)ei)[NE + e];
}

// ---------------- CSR build ----------------
__global__ void k_zero_deg() {
    int i = blockIdx.x * blockDim.x + threadIdx.x;
    if (i < NN) g_deg[i] = 0;
}

__global__ void k_hist(const void* __restrict__ ei) {
    const int is64 = g_is64;
    int stride = gridDim.x * blockDim.x;
    for (int e = blockIdx.x * blockDim.x + threadIdx.x; e < NE; e += stride) {
        int d = edge_dst(ei, e, is64);
        atomicAdd(&g_deg[d], 1);
    }
}

__global__ void k_dis(int b) {
    int i = blockIdx.x * blockDim.x + threadIdx.x;
    if (i < NN) g_dis[b][i] = rsqrtf((float)g_deg[i] + 1.0f);
}

// Exclusive prefix sum of g_deg -> g_rowptr[b], g_cur. One block, 1024 threads.
__global__ void k_scan(int b) {
    __shared__ int sm[1024];
    const int tid = threadIdx.x;
    const int CH = (NN + 1023) / 1024;  // 49
    int base = tid * CH;
    int s = 0;
    for (int i = 0; i < CH; i++) {
        int idx = base + i;
        if (idx < NN) s += g_deg[idx];
    }
    sm[tid] = s;
    __syncthreads();
    for (int off = 1; off < 1024; off <<= 1) {
        int v = (tid >= off) ? sm[tid - off] : 0;
        __syncthreads();
        sm[tid] += v;
        __syncthreads();
    }
    int run = (tid == 0) ? 0 : sm[tid - 1];
    for (int i = 0; i < CH; i++) {
        int idx = base + i;
        if (idx < NN) {
            g_rowptr[b][idx] = run;
            g_cur[idx] = run;
            run += g_deg[idx];
        }
    }
    if (tid == 1023) g_rowptr[b][NN] = sm[1023];
}

__global__ void k_scatter(const void* __restrict__ ei, int b) {
    const int is64 = g_is64;
    int stride = gridDim.x * blockDim.x;
    for (int e = blockIdx.x * blockDim.x + threadIdx.x; e < NE; e += stride) {
        int s = edge_src(ei, e, is64);
        int d = edge_dst(ei, e, is64);
        int p = atomicAdd(&g_cur[d], 1);
        g_col[b][p] = s;
        g_val[b][p] = g_dis[b][s] * g_dis[b][d];
    }
}

// ---------------- init: g_x = x0, g_tmp[0] = x0 @ W ----------------
__global__ void __launch_bounds__(256, 4) k_init(const float* __restrict__ x0,
                                                 const float* __restrict__ W) {
    const int lane = threadIdx.x & 31;
    float Wc[32];
#pragma unroll
    for (int d = 0; d < 32; d++) Wc[d] = __ldg(&W[d * 32 + lane]);
    int warpId = (blockIdx.x * blockDim.x + threadIdx.x) >> 5;
    int nw = (gridDim.x * blockDim.x) >> 5;
    for (int r = warpId; r < NN; r += nw) {
        float xv = x0[r * 32 + lane];
        g_x[r * 32 + lane] = xv;
        float o = 0.f;
#pragma unroll
        for (int d = 0; d < 32; d++)
            o += __shfl_sync(0xffffffffu, xv, d) * Wc[d];
        g_tmp[0][r * 32 + lane] = o;
    }
}

// ---------------- fused RK4 stage: SpMM + gate/relu + state update + y@W ----------------
// tin = g_tmp[pin] = (y_stage @ W); tout = g_tmp[pin^1] = (y_nextstage @ W).
// STAGE 1: ksum  = k;   y' = x + H/2 k
// STAGE 2: ksum += 2k;  y' = x + H/2 k
// STAGE 3: ksum += 2k;  y' = x + H   k
// STAGE 4: xnew = x + H/6 (ksum + k); write xnew to g_x or xout; y' = xnew
template <int STAGE>
__global__ void __launch_bounds__(256, 4) k_stage(
    int pin, int b,
    const float* __restrict__ W, const float* __restrict__ bvec,
    const float* __restrict__ wt, float t, float* __restrict__ xout) {
    const float* __restrict__ tin  = g_tmp[pin];
    float* __restrict__ tout = g_tmp[pin ^ 1];
    const int* __restrict__ col = g_col[b];
    const float* __restrict__ val = g_val[b];
    const int* __restrict__ rowptr = g_rowptr[b];
    const float* __restrict__ dis = g_dis[b];

    const int lane = threadIdx.x & 31;
    float Wc[32];
#pragma unroll
    for (int d = 0; d < 32; d++) Wc[d] = __ldg(&W[d * 32 + lane]);
    const float bb = __ldg(&bvec[lane]);
    const float wl = __ldg(&wt[lane]);
    const float gate = 1.0f / (1.0f + __expf(-t * wl));

    int warpId = (blockIdx.x * blockDim.x + threadIdx.x) >> 5;
    int nw = (gridDim.x * blockDim.x) >> 5;
    for (int r = warpId; r < NN; r += nw) {
        const int st = rowptr[r];
        const int en = rowptr[r + 1];
        float acc = 0.f;
        int e = st;
        for (; e + 4 <= en; e += 4) {
            int c0 = col[e], c1 = col[e + 1], c2 = col[e + 2], c3 = col[e + 3];
            float v0 = val[e], v1 = val[e + 1], v2 = val[e + 2], v3 = val[e + 3];
            float a0 = tin[c0 * 32 + lane];
            float a1 = tin[c1 * 32 + lane];
            float a2 = tin[c2 * 32 + lane];
            float a3 = tin[c3 * 32 + lane];
            acc += v0 * a0;
            acc += v1 * a1;
            acc += v2 * a2;
            acc += v3 * a3;
        }
        for (; e < en; e++) acc += val[e] * tin[col[e] * 32 + lane];

        const float dn = dis[r];
        float agg = acc + dn * dn * tin[r * 32 + lane] + bb;
        float k = fmaxf(agg, 0.f) * gate;
        float xv = g_x[r * 32 + lane];
        float y;
        if (STAGE == 1) {
            g_ksum[r * 32 + lane] = k;
            y = xv + 0.5f * Hstep * k;
        } else if (STAGE == 2) {
            g_ksum[r * 32 + lane] += 2.f * k;
            y = xv + 0.5f * Hstep * k;
        } else if (STAGE == 3) {
            g_ksum[r * 32 + lane] += 2.f * k;
            y = xv + Hstep * k;
        } else {
            float ks = g_ksum[r * 32 + lane];
            y = xv + (Hstep / 6.f) * (ks + k);
            if (xout) xout[r * 32 + lane] = y;
            else      g_x[r * 32 + lane] = y;
        }
        float o = 0.f;
#pragma unroll
        for (int d = 0; d < 32; d++)
            o += __shfl_sync(0xffffffffu, y, d) * Wc[d];
        tout[r * 32 + lane] = o;
    }
}

// ---------------- host ----------------
extern "C" void kernel_launch(void* const* d_in, const int* in_sizes, int n_in,
                              void* d_out, int out_size) {
    const float* x0 = (const float*)d_in[0];
    const void* epos = d_in[1];
    const void* eneg = d_in[2];
    const float* Wp = (const float*)d_in[3];
    const float* bp = (const float*)d_in[4];
    const float* wtp = (const float*)d_in[5];
    const float* Wn = (const float*)d_in[6];
    const float* bn = (const float*)d_in[7];
    const float* wtn = (const float*)d_in[8];
    float* out = (float*)d_out;

    const int SPMM_BLOCKS = 592;  // 4 blocks/SM x 148 SMs
    const int EDGE_BLOCKS = 1184;

    k_probe<<<1, 1024>>>((const int*)epos);

    for (int b = 0; b < 2; b++) {
        const void* ei = b ? eneg : epos;
        const float* W = b ? Wn : Wp;
        const float* bv = b ? bn : bp;
        const float* wt = b ? wtn : wtp;

        // Build CSR (by dst) + normalization coefficients
        k_zero_deg<<<(NN + 255) / 256, 256>>>();
        k_hist<<<EDGE_BLOCKS, 256>>>(ei);
        k_dis<<<(NN + 255) / 256, 256>>>(b);
        k_scan<<<1, 1024>>>(b);
        k_scatter<<<EDGE_BLOCKS, 256>>>(ei, b);

        // g_x = x0, g_tmp[0] = x0 @ W
        k_init<<<SPMM_BLOCKS, 256>>>(x0, W);

        int pin = 0;
        for (int step = 0; step < 10; step++) {
            float t = step * Hstep;
            k_stage<1><<<SPMM_BLOCKS, 256>>>(pin, b, W, bv, wt, t, nullptr);
            pin ^= 1;
            k_stage<2><<<SPMM_BLOCKS, 256>>>(pin, b, W, bv, wt, t + 0.5f * Hstep, nullptr);
            pin ^= 1;
            k_stage<3><<<SPMM_BLOCKS, 256>>>(pin, b, W, bv, wt, t + 0.5f * Hstep, nullptr);
            pin ^= 1;
            float* xo = (step == 9) ? (out + (size_t)b * NN * DD) : nullptr;
            k_stage<4><<<SPMM_BLOCKS, 256>>>(pin, b, W, bv, wt, t + Hstep, xo);
            pin ^= 1;
        }
    }
}

// round 4
// speedup vs baseline: 1.2684x; 1.2684x over previous
#include <cuda_runtime.h>

#define NN 50000
#define NE 1600000
#define DD 32
static constexpr float Hstep = 0.1f;

// ---------------- static device scratch ----------------
__device__ int   g_is64;
__device__ int   g_deg[NN];
__device__ int   g_cur[NN];
__device__ int   g_rowptr[2][NN + 1];
__device__ __align__(16) int2  g_colval[2][NE];
__device__ float g_dis[2][NN];
__device__ __align__(128) float g_tmp[2][NN * DD];   // ping-pong (y @ W)
__device__ __align__(128) float g_x[NN * DD];
__device__ __align__(128) float g_ksum[NN * DD];

// ---------------- edge readers (dtype-agnostic) ----------------
__device__ __forceinline__ int edge_src(const void* ei, int e, int is64) {
    if (is64) return (int)((const long long*)ei)[e];
    return ((const int*)ei)[e];
}
__device__ __forceinline__ int edge_dst(const void* ei, int e, int is64) {
    if (is64) return (int)((const long long*)ei)[NE + e];
    return ((const int*)ei)[NE + e];
}

// ---------------- setup: probe dtype + zero degree ----------------
__global__ void k_probe_zero(const int* __restrict__ w) {
    if (blockIdx.x == 0) {
        __shared__ int anynz;
        if (threadIdx.x == 0) anynz = 0;
        __syncthreads();
        // int64 little-endian: odd words of first 256 elements are all 0 (< 50000)
        if (w[2 * threadIdx.x + 1] != 0) atomicOr(&anynz, 1);
        __syncthreads();
        if (threadIdx.x == 0) g_is64 = (anynz == 0) ? 1 : 0;
    }
    int i = blockIdx.x * blockDim.x + threadIdx.x;
    int stride = gridDim.x * blockDim.x;
    for (; i < NN; i += stride) g_deg[i] = 0;
}

__global__ void k_hist(const void* __restrict__ ei) {
    const int is64 = g_is64;
    int stride = gridDim.x * blockDim.x;
    for (int e = blockIdx.x * blockDim.x + threadIdx.x; e < NE; e += stride) {
        int d = edge_dst(ei, e, is64);
        atomicAdd(&g_deg[d], 1);
    }
}

// dis = rsqrt(deg+1); exclusive scan of deg -> rowptr, cur. One block.
__global__ void k_scan_dis(int b) {
    __shared__ int sm[1024];
    const int tid = threadIdx.x;
    const int CH = (NN + 1023) / 1024;  // 49
    int base = tid * CH;
    int s = 0;
    for (int i = 0; i < CH; i++) {
        int idx = base + i;
        if (idx < NN) {
            int d = g_deg[idx];
            g_dis[b][idx] = rsqrtf((float)d + 1.0f);
            s += d;
        }
    }
    sm[tid] = s;
    __syncthreads();
    for (int off = 1; off < 1024; off <<= 1) {
        int v = (tid >= off) ? sm[tid - off] : 0;
        __syncthreads();
        sm[tid] += v;
        __syncthreads();
    }
    int run = (tid == 0) ? 0 : sm[tid - 1];
    for (int i = 0; i < CH; i++) {
        int idx = base + i;
        if (idx < NN) {
            g_rowptr[b][idx] = run;
            g_cur[idx] = run;
            run += g_deg[idx];
        }
    }
    if (tid == 1023) g_rowptr[b][NN] = sm[1023];
}

// blocks [0,EB): scatter edges into CSR; blocks [EB,EB+IB): g_x=x0, tmp[0]=x0@W
__global__ void __launch_bounds__(256) k_scatter_init(
    const void* __restrict__ ei, int b, int EB,
    const float* __restrict__ x0, const float* __restrict__ W) {
    if (blockIdx.x < EB) {
        const int is64 = g_is64;
        int stride = EB * blockDim.x;
        for (int e = blockIdx.x * blockDim.x + threadIdx.x; e < NE; e += stride) {
            int s = edge_src(ei, e, is64);
            int d = edge_dst(ei, e, is64);
            int p = atomicAdd(&g_cur[d], 1);
            int2 cv;
            cv.x = s;
            cv.y = __float_as_int(g_dis[b][s] * g_dis[b][d]);
            g_colval[b][p] = cv;
        }
    } else {
        const int lane = threadIdx.x & 31;
        float Wc[32];
#pragma unroll
        for (int d = 0; d < 32; d++) Wc[d] = __ldg(&W[d * 32 + lane]);
        int warpId = ((blockIdx.x - EB) * blockDim.x + threadIdx.x) >> 5;
        int nw = ((gridDim.x - EB) * blockDim.x) >> 5;
        for (int r = warpId; r < NN; r += nw) {
            float xv = x0[r * 32 + lane];
            g_x[r * 32 + lane] = xv;
            float o = 0.f;
#pragma unroll
            for (int d = 0; d < 32; d++)
                o += __shfl_sync(0xffffffffu, xv, d) * Wc[d];
            g_tmp[0][r * 32 + lane] = o;
        }
    }
}

// ---------------- fused RK4 stage ----------------
// Quarter-warp per row: 4 rows/warp, 8 lanes x float4 per row.
// STAGE 1: ksum  = k;   y = x + H/2 k
// STAGE 2: ksum += 2k;  y = x + H/2 k
// STAGE 3: ksum += 2k;  y = x + H   k
// STAGE 4: y = x + H/6 (ksum + k); write y to g_x or xout
// Always: tout = y @ W
template <int STAGE>
__global__ void __launch_bounds__(256, 3) k_stage(
    int pin, int b,
    const float* __restrict__ W, const float* __restrict__ bvec,
    const float* __restrict__ wt, float t, float* __restrict__ xout) {
    const float* __restrict__ tin = g_tmp[pin];
    float* __restrict__ tout = g_tmp[pin ^ 1];
    const int2* __restrict__ colval = g_colval[b];
    const int* __restrict__ rowptr = g_rowptr[b];
    const float* __restrict__ dis = g_dis[b];

    const int lane = threadIdx.x & 31;
    const int li = lane & 7;      // lane within 8-lane group
    // Per-output-column weight column (for y @ W epilogue)
    float Wc[32];
#pragma unroll
    for (int d = 0; d < 32; d++) Wc[d] = __ldg(&W[d * 32 + lane]);
    // Per-owned-dim params: this lane owns dims li*4 .. li*4+3 of its row
    const float4 bb = *(const float4*)(bvec + li * 4);
    const float4 wl = *(const float4*)(wt + li * 4);
    float4 gate;
    gate.x = 1.0f / (1.0f + __expf(-t * wl.x));
    gate.y = 1.0f / (1.0f + __expf(-t * wl.y));
    gate.z = 1.0f / (1.0f + __expf(-t * wl.z));
    gate.w = 1.0f / (1.0f + __expf(-t * wl.w));

    int warpId = (blockIdx.x * blockDim.x + threadIdx.x) >> 5;
    int nw = (gridDim.x * blockDim.x) >> 5;
    const int g = lane >> 3;      // group id = which of 4 rows

    for (int rb = warpId * 4; rb < NN; rb += nw * 4) {
        const int r = rb + g;
        const int st = rowptr[r];
        const int en = rowptr[r + 1];
        float4 acc = make_float4(0.f, 0.f, 0.f, 0.f);
#pragma unroll 4
        for (int e = st; e < en; e++) {
            const int2 cv = __ldg(&colval[e]);          // broadcast in group
            const float v = __int_as_float(cv.y);
            const float4 a = *(const float4*)(tin + (size_t)cv.x * 32 + li * 4);
            acc.x += v * a.x;
            acc.y += v * a.y;
            acc.z += v * a.z;
            acc.w += v * a.w;
        }
        const float dn = dis[r];
        const float sn = dn * dn;
        const float4 sv = *(const float4*)(tin + (size_t)r * 32 + li * 4);
        float4 k4;
        k4.x = fmaxf(acc.x + sn * sv.x + bb.x, 0.f) * gate.x;
        k4.y = fmaxf(acc.y + sn * sv.y + bb.y, 0.f) * gate.y;
        k4.z = fmaxf(acc.z + sn * sv.z + bb.z, 0.f) * gate.z;
        k4.w = fmaxf(acc.w + sn * sv.w + bb.w, 0.f) * gate.w;

        const float4 xv = *(const float4*)(g_x + (size_t)r * 32 + li * 4);
        float4* ksp = (float4*)(g_ksum + (size_t)r * 32 + li * 4);
        float4 y;
        if (STAGE == 1) {
            *ksp = k4;
            y.x = xv.x + 0.5f * Hstep * k4.x;
            y.y = xv.y + 0.5f * Hstep * k4.y;
            y.z = xv.z + 0.5f * Hstep * k4.z;
            y.w = xv.w + 0.5f * Hstep * k4.w;
        } else if (STAGE == 2) {
            float4 ks = *ksp;
            ks.x += 2.f * k4.x; ks.y += 2.f * k4.y;
            ks.z += 2.f * k4.z; ks.w += 2.f * k4.w;
            *ksp = ks;
            y.x = xv.x + 0.5f * Hstep * k4.x;
            y.y = xv.y + 0.5f * Hstep * k4.y;
            y.z = xv.z + 0.5f * Hstep * k4.z;
            y.w = xv.w + 0.5f * Hstep * k4.w;
        } else if (STAGE == 3) {
            float4 ks = *ksp;
            ks.x += 2.f * k4.x; ks.y += 2.f * k4.y;
            ks.z += 2.f * k4.z; ks.w += 2.f * k4.w;
            *ksp = ks;
            y.x = xv.x + Hstep * k4.x;
            y.y = xv.y + Hstep * k4.y;
            y.z = xv.z + Hstep * k4.z;
            y.w = xv.w + Hstep * k4.w;
        } else {
            const float4 ks = *ksp;
            y.x = xv.x + (Hstep / 6.f) * (ks.x + k4.x);
            y.y = xv.y + (Hstep / 6.f) * (ks.y + k4.y);
            y.z = xv.z + (Hstep / 6.f) * (ks.z + k4.z);
            y.w = xv.w + (Hstep / 6.f) * (ks.w + k4.w);
            if (xout) *(float4*)(xout + (size_t)r * 32 + li * 4) = y;
            else      *(float4*)(g_x + (size_t)r * 32 + li * 4) = y;
        }

        // Epilogue: tout[row_j] = y_j @ W, serialized over the 4 rows.
        // Dim d of row j lives in lane 8*j + (d>>2), component d&3.
#pragma unroll
        for (int j = 0; j < 4; j++) {
            float o = 0.f;
#pragma unroll
            for (int dq = 0; dq < 8; dq++) {
                const int srcl = 8 * j + dq;
                o += __shfl_sync(0xffffffffu, y.x, srcl) * Wc[4 * dq + 0];
                o += __shfl_sync(0xffffffffu, y.y, srcl) * Wc[4 * dq + 1];
                o += __shfl_sync(0xffffffffu, y.z, srcl) * Wc[4 * dq + 2];
                o += __shfl_sync(0xffffffffu, y.w, srcl) * Wc[4 * dq + 3];
            }
            tout[(size_t)(rb + j) * 32 + lane] = o;
        }
    }
}

// ---------------- host ----------------
extern "C" void kernel_launch(void* const* d_in, const int* in_sizes, int n_in,
                              void* d_out, int out_size) {
    const float* x0 = (const float*)d_in[0];
    const void* epos = d_in[1];
    const void* eneg = d_in[2];
    const float* Wp = (const float*)d_in[3];
    const float* bp = (const float*)d_in[4];
    const float* wtp = (const float*)d_in[5];
    const float* Wn = (const float*)d_in[6];
    const float* bn = (const float*)d_in[7];
    const float* wtn = (const float*)d_in[8];
    float* out = (float*)d_out;

    const int SPMM_BLOCKS = 444;   // 3 blocks/SM x 148 SMs
    const int EDGE_BLOCKS = 1184;
    const int INIT_BLOCKS = 444;

    for (int b = 0; b < 2; b++) {
        const void* ei = b ? eneg : epos;
        const float* W = b ? Wn : Wp;
        const float* bv = b ? bn : bp;
        const float* wt = b ? wtn : wtp;

        k_probe_zero<<<196, 256>>>((const int*)epos);
        k_hist<<<EDGE_BLOCKS, 256>>>(ei);
        k_scan_dis<<<1, 1024>>>(b);
        k_scatter_init<<<EDGE_BLOCKS + INIT_BLOCKS, 256>>>(ei, b, EDGE_BLOCKS, x0, W);

        int pin = 0;
        for (int step = 0; step < 10; step++) {
            float t = step * Hstep;
            k_stage<1><<<SPMM_BLOCKS, 256>>>(pin, b, W, bv, wt, t, nullptr);
            pin ^= 1;
            k_stage<2><<<SPMM_BLOCKS, 256>>>(pin, b, W, bv, wt, t + 0.5f * Hstep, nullptr);
            pin ^= 1;
            k_stage<3><<<SPMM_BLOCKS, 256>>>(pin, b, W, bv, wt, t + 0.5f * Hstep, nullptr);
            pin ^= 1;
            float* xo = (step == 9) ? (out + (size_t)b * NN * DD) : nullptr;
            k_stage<4><<<SPMM_BLOCKS, 256>>>(pin, b, W, bv, wt, t + Hstep, xo);
            pin ^= 1;
        }
    }
}